// round 9
// baseline (speedup 1.0000x reference)
#include <cuda_runtime.h>
#include <cstdint>

// SpanRepresentation: out[b, span, :] = concat(x[b, start], x[b, end], width_emb[w-1])
//   x: (16, 512, 768) f32, width_emb: (8, 64) f32, L = 512
//   spans: width w=1..8, start s=0..L-w  -> 4068 spans
//   out: (16, 4068, 1600) f32
//
// R8: TMA bulk stores (kept from R7 — best DRAM% so far) with the
// serialization removed:
//   - per-half named barriers (bar.sync 1/2, 128) instead of __syncthreads
//   - one 6400B bulk store per half, issued by that half's elected thread
//   - only the 2 elected threads wait on the bulk group at the tail
//   - evict-first L2 policy on the output stream (parity with __stcs)

namespace {

constexpr int B  = 16;
constexpr int L  = 512;
constexpr int D  = 768;
constexpr int WD = 64;

// cumulative span offsets per width index wi (0-based): off[wi] = wi*L - wi*(wi-1)/2
constexpr int OFF1 = 1 * L - 0;            // 512
constexpr int OFF2 = 2 * L - 1;            // 1023
constexpr int OFF3 = 3 * L - 3;            // 1533
constexpr int OFF4 = 4 * L - 6;            // 2042
constexpr int OFF5 = 5 * L - 10;           // 2550
constexpr int OFF6 = 6 * L - 15;           // 3057
constexpr int OFF7 = 7 * L - 21;           // 3563
constexpr int NSPANS = 8 * L - 28;         // 4068 (even)

constexpr int D4    = D / 4;               // 192 float4 per x row
constexpr int WD4   = WD / 4;              // 16 float4 per width_emb row
constexpr int ROW4  = 2 * D4 + WD4;        // 400 float4 per output row (6400 B)
constexpr int ROW_B = ROW4 * 16;           // 6400 bytes

constexpr int THREADS = 256;               // two 128-thread halves, one span each

} // namespace

__global__ __launch_bounds__(THREADS, 8)
void span_repr_kernel(const float4* __restrict__ x,
                      const float4* __restrict__ wemb,
                      float4* __restrict__ out)
{
    __shared__ alignas(128) float4 buf[2 * ROW4];   // 12800 B

    const int half = threadIdx.x >> 7;            // 0 or 1 (warp-aligned split)
    const int t    = threadIdx.x & 127;           // lane within the half
    const int span = blockIdx.x * 2 + half;       // 0..NSPANS-1
    const int b    = blockIdx.y;                  // 0..B-1

    // width index via 7 compares against constexpr cumulative offsets
    int wi = 0;
    if (span >= OFF1) wi = 1;
    if (span >= OFF2) wi = 2;
    if (span >= OFF3) wi = 3;
    if (span >= OFF4) wi = 4;
    if (span >= OFF5) wi = 5;
    if (span >= OFF6) wi = 6;
    if (span >= OFF7) wi = 7;

    int off;
    switch (wi) {
        case 0: off = 0;    break;
        case 1: off = OFF1; break;
        case 2: off = OFF2; break;
        case 3: off = OFF3; break;
        case 4: off = OFF4; break;
        case 5: off = OFF5; break;
        case 6: off = OFF6; break;
        default: off = OFF7; break;
    }
    const int s = span - off;          // start position
    const int e = s + wi;              // end position (= s + w - 1)

    const float4* __restrict__ xs = x + (size_t)(b * L + s) * D4;
    const float4* __restrict__ xe = x + (size_t)(b * L + e) * D4;
    const float4* __restrict__ we = wemb + wi * WD4;

    // Gather 400 float4 into this half's SMEM row.
    float4* row = buf + half * ROW4;
    #pragma unroll
    for (int j = 0; j < 4; ++j) {
        const int idx = t + j * 128;
        if (idx < D4) {
            row[idx] = __ldg(xs + idx);
        } else if (idx < 2 * D4) {
            row[idx] = __ldg(xe + (idx - D4));
        } else if (idx < ROW4) {
            row[idx] = __ldg(we + (idx - 2 * D4));
        }
    }

    // Sync only this half's 128 threads (named barrier 1 or 2).
    asm volatile("bar.sync %0, 128;" :: "r"(half + 1) : "memory");

    // Elected thread of each half issues one 6400B bulk store of its row,
    // with an evict-first L2 policy (output is a pure write-once stream).
    if (t == 0) {
        float4* o = out + ((size_t)b * NSPANS + span) * (size_t)ROW4;
        uint32_t saddr;
        asm("{ .reg .u64 tmp; cvta.to.shared.u64 tmp, %1; cvt.u32.u64 %0, tmp; }"
            : "=r"(saddr) : "l"(row));
        uint64_t pol;
        asm("createpolicy.fractional.L2::evict_first.b64 %0, 1.0;" : "=l"(pol));
        asm volatile("fence.proxy.async.shared::cta;" ::: "memory");
        asm volatile("cp.async.bulk.global.shared::cta.bulk_group.L2::cache_hint"
                     " [%0], [%1], %2, %3;"
                     :: "l"(o), "r"(saddr), "n"(ROW_B), "l"(pol) : "memory");
        asm volatile("cp.async.bulk.commit_group;" ::: "memory");
        asm volatile("cp.async.bulk.wait_group 0;" ::: "memory");
    }
}

extern "C" void kernel_launch(void* const* d_in, const int* in_sizes, int n_in,
                              void* d_out, int out_size)
{
    const float4* x    = (const float4*)d_in[0];   // (16, 512, 768) f32
    const float4* wemb = (const float4*)d_in[1];   // (8, 64) f32
    // d_in[2] = batch_max_seq_len (== 512, fixed for this instance) — unused
    float4* out = (float4*)d_out;

    dim3 grid(NSPANS / 2, B);
    span_repr_kernel<<<grid, THREADS>>>(x, wemb, out);
}

// round 11
// speedup vs baseline: 1.0730x; 1.0730x over previous
#include <cuda_runtime.h>
#include <cstdint>

// SpanRepresentation: out[b, span, :] = concat(x[b, start], x[b, end], width_emb[w-1])
//   x: (16, 512, 768) f32, width_emb: (8, 64) f32, L = 512
//   spans: width w=1..8, start s=0..L-w  -> 4068 spans
//   out: (16, 4068, 1600) f32
//
// R9: back to the register path (TMA-store family regressed twice: R7 66.3,
// R8 68.7 vs R4 64.3). Extend the only lever that produced a real win —
// span packing: 4 consecutive spans per 512-thread CTA (one span per
// 128-thread quad). 25.6KB contiguous output per CTA for DRAM page
// locality; CTA count drops to 16272.

namespace {

constexpr int B  = 16;
constexpr int L  = 512;
constexpr int D  = 768;
constexpr int WD = 64;

// cumulative span offsets per width index wi (0-based): off[wi] = wi*L - wi*(wi-1)/2
constexpr int OFF1 = 1 * L - 0;            // 512
constexpr int OFF2 = 2 * L - 1;            // 1023
constexpr int OFF3 = 3 * L - 3;            // 1533
constexpr int OFF4 = 4 * L - 6;            // 2042
constexpr int OFF5 = 5 * L - 10;           // 2550
constexpr int OFF6 = 6 * L - 15;           // 3057
constexpr int OFF7 = 7 * L - 21;           // 3563
constexpr int NSPANS = 8 * L - 28;         // 4068 (divisible by 4)

constexpr int D4    = D / 4;               // 192 float4 per x row
constexpr int WD4   = WD / 4;              // 16 float4 per width_emb row
constexpr int ROW4  = 2 * D4 + WD4;        // 400 float4 per output row (6400 B)

constexpr int THREADS = 512;               // four 128-thread quads, one span each
constexpr int SPANS_PER_CTA = 4;

} // namespace

__global__ __launch_bounds__(THREADS, 4)
void span_repr_kernel(const float4* __restrict__ x,
                      const float4* __restrict__ wemb,
                      float4* __restrict__ out)
{
    const int quad = threadIdx.x >> 7;            // 0..3 (warp-aligned split)
    const int t    = threadIdx.x & 127;           // lane within the quad
    const int span = blockIdx.x * SPANS_PER_CTA + quad;  // 0..NSPANS-1
    const int b    = blockIdx.y;                  // 0..B-1

    // width index via 7 compares against constexpr cumulative offsets
    int wi = 0;
    if (span >= OFF1) wi = 1;
    if (span >= OFF2) wi = 2;
    if (span >= OFF3) wi = 3;
    if (span >= OFF4) wi = 4;
    if (span >= OFF5) wi = 5;
    if (span >= OFF6) wi = 6;
    if (span >= OFF7) wi = 7;

    int off;
    switch (wi) {
        case 0: off = 0;    break;
        case 1: off = OFF1; break;
        case 2: off = OFF2; break;
        case 3: off = OFF3; break;
        case 4: off = OFF4; break;
        case 5: off = OFF5; break;
        case 6: off = OFF6; break;
        default: off = OFF7; break;
    }
    const int s = span - off;          // start position
    const int e = s + wi;              // end position (= s + w - 1)

    const float4* __restrict__ xs = x + (size_t)(b * L + s) * D4;
    const float4* __restrict__ xe = x + (size_t)(b * L + e) * D4;
    const float4* __restrict__ we = wemb + wi * WD4;
    float4* __restrict__ o = out + (size_t)(b * NSPANS + span) * (size_t)ROW4;

    // 400 float4 per row; 128 threads per quad -> 4 strided passes (last partial)
    #pragma unroll
    for (int j = 0; j < 4; ++j) {
        const int idx = t + j * 128;
        if (idx < D4) {
            __stcs(o + idx, __ldg(xs + idx));
        } else if (idx < 2 * D4) {
            __stcs(o + idx, __ldg(xe + (idx - D4)));
        } else if (idx < ROW4) {
            __stcs(o + idx, __ldg(we + (idx - 2 * D4)));
        }
    }
}

extern "C" void kernel_launch(void* const* d_in, const int* in_sizes, int n_in,
                              void* d_out, int out_size)
{
    const float4* x    = (const float4*)d_in[0];   // (16, 512, 768) f32
    const float4* wemb = (const float4*)d_in[1];   // (8, 64) f32
    // d_in[2] = batch_max_seq_len (== 512, fixed for this instance) — unused
    float4* out = (float4*)d_out;

    dim3 grid(NSPANS / SPANS_PER_CTA, B);
    span_repr_kernel<<<grid, THREADS>>>(x, wemb, out);
}